// round 17
// baseline (speedup 1.0000x reference)
#include <cuda_runtime.h>

// SSIM, fully fused, single kernel. X,Y: f32[32,3,512,512] -> scalar mean SSIM.
//
// Occupancy push: 5 CTAs/SM (40 warps). Register budget <=51/thread:
//  - phase 2 is pure scalar FFMA-imm (weights are immediates -> ZERO weight regs)
//  - phase 1 keeps only sv[14], dv[14] live and splits the tap loop into two
//    field passes (A: s,d conv; B: ss,dd squared on the fly)
//  - s = fma(x,1,y), d = fma(y,-1,x): FFMA-imm (rt=1)
// Sum/diff transform: only 4 conv fields {s,d,s^2,d^2}.
// TW=32 x TH=64, smem planes mu u64[74][32] {h_s,h_d}, sq u64[74][32]
// {h_ss,h_dd} = 37.9KB (x5 = 189.4KB/SM).
// Phase 1 (8 col-quads x 32 rows, statically peeled 2+1).
// Phase 2 (16 col-pairs x 16 row-groups, 4 vrows x 2 cols), 2x LDS.128 per tap.
// Epilogue: 8x-folded algebra. Block partials -> last block reduces.

#define TW 32
#define TH 64
#define NHR (TH + 10)   // 74
#define NTHR 256
#define GX 16
#define GY 8
#define GZ 96
#define NBLOCKS (GX * GY * GZ)

#define MU_OFF 0
#define SQ_OFF (NHR * TW * 8)          // 18944
#define SMEM_BYTES (2 * NHR * TW * 8)  // 37888

typedef unsigned long long u64;

__device__ float g_partials[NBLOCKS];
__device__ unsigned int g_count = 0;

// scalar: acc += v * w[k], w[k] immediate multiplier (FFMA-imm, rt=1).
__device__ __forceinline__ void fmaw(const int k, const float v, float& a) {
    switch (k) {
    case 0:  asm("fma.rn.f32 %0, %1, 0f3A86CAB5, %0;" : "+f"(a) : "f"(v)); break;
    case 1:  asm("fma.rn.f32 %0, %1, 0f3BF8FF05, %0;" : "+f"(a) : "f"(v)); break;
    case 2:  asm("fma.rn.f32 %0, %1, 0f3D137590, %0;" : "+f"(a) : "f"(v)); break;
    case 3:  asm("fma.rn.f32 %0, %1, 0f3DDFF883, %0;" : "+f"(a) : "f"(v)); break;
    case 4:  asm("fma.rn.f32 %0, %1, 0f3E5A1E20, %0;" : "+f"(a) : "f"(v)); break;
    case 5:  asm("fma.rn.f32 %0, %1, 0f3E8832B1, %0;" : "+f"(a) : "f"(v)); break;
    case 6:  asm("fma.rn.f32 %0, %1, 0f3E5A1E20, %0;" : "+f"(a) : "f"(v)); break;
    case 7:  asm("fma.rn.f32 %0, %1, 0f3DDFF883, %0;" : "+f"(a) : "f"(v)); break;
    case 8:  asm("fma.rn.f32 %0, %1, 0f3D137590, %0;" : "+f"(a) : "f"(v)); break;
    case 9:  asm("fma.rn.f32 %0, %1, 0f3BF8FF05, %0;" : "+f"(a) : "f"(v)); break;
    case 10: asm("fma.rn.f32 %0, %1, 0f3A86CAB5, %0;" : "+f"(a) : "f"(v)); break;
    default: break;
    }
}

// s = x + y as FFMA-imm (x*1.0 + y), rt=1.
__device__ __forceinline__ float fadd1(const float x, const float y) {
    float r;
    asm("fma.rn.f32 %0, %1, 0f3F800000, %2;" : "=f"(r) : "f"(x), "f"(y));
    return r;
}
// d = x - y as FFMA-imm (y*-1.0 + x), rt=1.
__device__ __forceinline__ float fsub1(const float x, const float y) {
    float r;
    asm("fma.rn.f32 %0, %1, 0fBF800000, %2;" : "=f"(r) : "f"(y), "f"(x));
    return r;
}

__device__ __forceinline__ u64 pk2(float lo, float hi) {
    u64 r;
    asm("mov.b64 %0, {%1, %2};" : "=l"(r) : "f"(lo), "f"(hi));
    return r;
}
__device__ __forceinline__ void upk2(float& lo, float& hi, u64 v) {
    asm("mov.b64 {%0, %1}, %2;" : "=f"(lo), "=f"(hi) : "l"(v));
}

// One horizontal-conv row: 4 cols from basec, store into smem row `hr`.
template <bool CHECK_R>
__device__ __forceinline__ void hconv_row(
    const float* __restrict__ Xi, const float* __restrict__ Yi,
    u64* __restrict__ sh_mu, u64* __restrict__ sh_sq,
    const int r0, const int hr, const int basec, const int q1) {
    const int gr = r0 + hr;
    const float* __restrict__ xr = Xi + (long)gr * 512;
    const float* __restrict__ yr = Yi + (long)gr * 512;
    const bool rok = CHECK_R ? (gr < 512) : true;

    // Only 14 window values are consumed (j+k <= 13); keep just sv/dv[14].
    float sv[14], dv[14];
#pragma unroll
    for (int q = 0; q < 4; q++) {
        const int qc = basec + 4 * q;
        float4 xq, yq;
        if (rok && qc < 512) {
            xq = *reinterpret_cast<const float4*>(xr + qc);
            yq = *reinterpret_cast<const float4*>(yr + qc);
        } else {
            xq = make_float4(0.f, 0.f, 0.f, 0.f);
            yq = make_float4(0.f, 0.f, 0.f, 0.f);
        }
        const float xs[4] = {xq.x, xq.y, xq.z, xq.w};
        const float ys[4] = {yq.x, yq.y, yq.z, yq.w};
#pragma unroll
        for (int e = 0; e < 4; e++) {
            const int idx = 4 * q + e;
            if (idx < 14) {
                sv[idx] = fadd1(xs[e], ys[e]);
                dv[idx] = fsub1(xs[e], ys[e]);
            }
        }
    }

    // Pass A: conv of s, d.
    float as[4], ad[4];
#pragma unroll
    for (int j = 0; j < 4; j++) { as[j] = 0.f; ad[j] = 0.f; }
#pragma unroll
    for (int t = 0; t < 14; t++) {
        const float st = sv[t], dt = dv[t];
#pragma unroll
        for (int j = 0; j < 4; j++) {
            const int k = t - j;
            if (k >= 0 && k <= 10) {
                fmaw(k, st, as[j]);
                fmaw(k, dt, ad[j]);
            }
        }
    }

    // Pass B: conv of s^2, d^2 (squares formed on the fly).
    float ass[4], add_[4];
#pragma unroll
    for (int j = 0; j < 4; j++) { ass[j] = 0.f; add_[j] = 0.f; }
#pragma unroll
    for (int t = 0; t < 14; t++) {
        const float sst = sv[t] * sv[t];
        const float ddt = dv[t] * dv[t];
#pragma unroll
        for (int j = 0; j < 4; j++) {
            const int k = t - j;
            if (k >= 0 && k <= 10) {
                fmaw(k, sst, ass[j]);
                fmaw(k, ddt, add_[j]);
            }
        }
    }

    // Pair at store time only: {h_s,h_d} and {h_ss,h_dd} interleaved planes.
    const int so = hr * TW + 4 * q1;
    *reinterpret_cast<ulonglong2*>(&sh_mu[so]) =
        make_ulonglong2(pk2(as[0], ad[0]), pk2(as[1], ad[1]));
    *reinterpret_cast<ulonglong2*>(&sh_mu[so + 2]) =
        make_ulonglong2(pk2(as[2], ad[2]), pk2(as[3], ad[3]));
    *reinterpret_cast<ulonglong2*>(&sh_sq[so]) =
        make_ulonglong2(pk2(ass[0], add_[0]), pk2(ass[1], add_[1]));
    *reinterpret_cast<ulonglong2*>(&sh_sq[so + 2]) =
        make_ulonglong2(pk2(ass[2], add_[2]), pk2(ass[3], add_[3]));
}

__global__ void __launch_bounds__(NTHR, 5)
ssim_main_kernel(const float* __restrict__ X, const float* __restrict__ Y,
                 float* __restrict__ out, double inv_count) {
    extern __shared__ char shb[];
    u64* sh_mu = reinterpret_cast<u64*>(shb + MU_OFF);  // [NHR][TW] {h_s,h_d}
    u64* sh_sq = reinterpret_cast<u64*>(shb + SQ_OFF);  // [NHR][TW] {h_ss,h_dd}

    const int tid = threadIdx.x;
    const int c0 = blockIdx.x * TW;
    const int r0 = blockIdx.y * TH;
    const long img = blockIdx.z;
    const float* __restrict__ Xi = X + img * (512L * 512L);
    const float* __restrict__ Yi = Y + img * (512L * 512L);

    // ---------------- Phase 1: statically peeled (2 + 1 predicated iters) -------
    {
        const int q1 = tid & 7;
        const int r1 = tid >> 3;   // 0..31
        const int basec = c0 + 4 * q1;
        hconv_row<false>(Xi, Yi, sh_mu, sh_sq, r0, r1,      basec, q1);
        hconv_row<false>(Xi, Yi, sh_mu, sh_sq, r0, r1 + 32, basec, q1);
        if (r1 < NHR - 64)   // rows 64..73
            hconv_row<true>(Xi, Yi, sh_mu, sh_sq, r0, r1 + 64, basec, q1);
    }
    __syncthreads();

    // ---------------- Phase 2: vertical conv, scalar FFMA-imm (no weight regs) --
    // Map B: 16 col-pairs x 16 row-groups (4 vrows x 2 cols per thread).
    const int tx2 = tid & 15;
    const int ty2 = tid >> 4;
    const int lr0 = ty2 * 4;
    const int scol = 2 * tx2;

    float a_s[4][2], a_d[4][2], a_ss[4][2], a_dd[4][2];
#pragma unroll
    for (int v = 0; v < 4; v++)
#pragma unroll
        for (int c = 0; c < 2; c++) {
            a_s[v][c] = 0.f; a_d[v][c] = 0.f;
            a_ss[v][c] = 0.f; a_dd[v][c] = 0.f;
        }

#pragma unroll
    for (int i = 0; i < 14; i++) {
        const int roff = (lr0 + i) * TW + scol;
        const ulonglong2 m = *reinterpret_cast<const ulonglong2*>(&sh_mu[roff]);
        const ulonglong2 s = *reinterpret_cast<const ulonglong2*>(&sh_sq[roff]);
        float hs0, hd0, hs1, hd1, hss0, hdd0, hss1, hdd1;
        upk2(hs0, hd0, m.x);
        upk2(hs1, hd1, m.y);
        upk2(hss0, hdd0, s.x);
        upk2(hss1, hdd1, s.y);
#pragma unroll
        for (int v = 0; v < 4; v++) {
            const int k = i - v;
            if (k >= 0 && k <= 10) {
                fmaw(k, hs0,  a_s[v][0]);  fmaw(k, hs1,  a_s[v][1]);
                fmaw(k, hd0,  a_d[v][0]);  fmaw(k, hd1,  a_d[v][1]);
                fmaw(k, hss0, a_ss[v][0]); fmaw(k, hss1, a_ss[v][1]);
                fmaw(k, hdd0, a_dd[v][0]); fmaw(k, hdd1, a_dd[v][1]);
            }
        }
    }

    // ---------------- Epilogue + reduction ----------------
    // 8x-folded: T8 = 4*mu_s + (4 + 8*C1); A=mu_s^2, B=mu_d^2;
    //   ln8=(A-B)+T8, ld8=(A+B)+T8; P=Ess-A, Q=Edd-B;
    //   cs=(P-Q+8C2)/(P+Q+8C2); ssim = cs*ln8/ld8.
    float lsum = 0.0f;
    const float T8C = 4.0f + 8e-4f;  // 4 + 8*C1
    const float C2x8 = 0.0072f;      // 8*(0.03)^2
#pragma unroll
    for (int v = 0; v < 4; v++) {
        const int orow = r0 + lr0 + v;
#pragma unroll
        for (int c = 0; c < 2; c++) {
            const int ocol = c0 + scol + c;
            const float ms = a_s[v][c];
            const float md = a_d[v][c];
            const float A = ms * ms;
            const float B = md * md;
            const float P = a_ss[v][c] - A;
            const float Q = a_dd[v][c] - B;
            const float T8 = fmaf(4.0f, ms, T8C);
            const float ln = (A - B) + T8;
            const float ld = (A + B) + T8;
            const float csn = (P - Q) + C2x8;
            const float csd = (P + Q) + C2x8;
            const float ssim = (csn * ln) * __fdividef(1.0f, csd * ld);
            lsum += (orow < 502 && ocol < 502) ? ssim : 0.0f;
        }
    }

#pragma unroll
    for (int off = 16; off > 0; off >>= 1)
        lsum += __shfl_xor_sync(0xffffffffu, lsum, off);

    __shared__ float wsum[8];
    __shared__ bool is_last;
    const int wid = tid >> 5;
    const int lid = tid & 31;
    if (lid == 0) wsum[wid] = lsum;
    __syncthreads();
    if (tid == 0) {
        float b = 0.0f;
#pragma unroll
        for (int w = 0; w < 8; w++) b += wsum[w];
        const int bi = blockIdx.x + gridDim.x * (blockIdx.y + gridDim.y * blockIdx.z);
        g_partials[bi] = b;
        __threadfence();
        const unsigned int n = atomicAdd(&g_count, 1u);
        is_last = (n == (unsigned int)(NBLOCKS - 1));
    }
    __syncthreads();

    if (is_last) {
        __threadfence();
        double s = 0.0;
        for (int i = tid; i < NBLOCKS; i += NTHR)
            s += (double)g_partials[i];
#pragma unroll
        for (int off = 16; off > 0; off >>= 1)
            s += __shfl_xor_sync(0xffffffffu, s, off);
        __shared__ double sd[8];
        if (lid == 0) sd[wid] = s;
        __syncthreads();
        if (tid == 0) {
            double tot = 0.0;
#pragma unroll
            for (int w = 0; w < 8; w++) tot += sd[w];
            out[0] = (float)(tot * inv_count);
            g_count = 0;  // reset for next graph replay
        }
    }
}

extern "C" void kernel_launch(void* const* d_in, const int* in_sizes, int n_in,
                              void* d_out, int out_size) {
    const float* X = (const float*)d_in[0];
    const float* Y = (const float*)d_in[1];
    float* out = (float*)d_out;

    const int images = in_sizes[0] / (512 * 512);  // 96
    const double count = (double)images * 502.0 * 502.0;

    cudaFuncSetAttribute(ssim_main_kernel,
                         cudaFuncAttributeMaxDynamicSharedMemorySize, SMEM_BYTES);

    dim3 grid(GX, GY, images);  // 16 x 8 x 96 = 12288 blocks
    ssim_main_kernel<<<grid, NTHR, SMEM_BYTES>>>(X, Y, out, 1.0 / count);
}